// round 1
// baseline (speedup 1.0000x reference)
#include <cuda_runtime.h>

#define D   16
#define LIB 969
#define TPB 256
#define ROWS_PER_BLOCK (2 * TPB)

// packed fp32x2 FMA (sm_100+): acc = m * c + acc, lanewise on two fp32 halves
#define FFMA2(acc, m, c) \
    asm("fma.rn.f32x2 %0, %1, %2, %0;" : "+l"(acc) : "l"(m), "l"(c))
// splat one fp32 into both halves of a b64
#define PACK2(dst, s) \
    asm("mov.b64 %0, {%1, %1};" : "=l"(dst) : "r"(__float_as_uint(s)))

__global__ __launch_bounds__(TPB, 2) void sindy_kernel(
    const float* __restrict__ z,
    const float* __restrict__ coeff,
    const float* __restrict__ fixedv,
    const unsigned char* __restrict__ fmask,
    float* __restrict__ out,
    int B)
{
    extern __shared__ float smem[];
    float* scf = smem;                    // LIB*D coeff floats (mask applied)
    float* zsA = smem + LIB * D;          // [D][TPB] row-A z values
    float* zsB = zsA + TPB * D;           // [D][TPB] row-B z values

    const int tid = threadIdx.x;

    // Stage coefficients with fixed_mask applied (broadcast-read later)
    for (int i = tid; i < LIB * D; i += TPB)
        scf[i] = fmask[i] ? fixedv[i] : coeff[i];

    const long r0 = (long)blockIdx.x * ROWS_PER_BLOCK + tid;
    const long r1 = r0 + TPB;
    const bool v0 = r0 < B;
    const bool v1 = r1 < B;

    // Load two z rows (16 floats each) via float4, zero-fill invalid rows
    float za[D], zb[D];
    {
        const float4* p0 = (const float4*)(z + r0 * D);
        const float4* p1 = (const float4*)(z + r1 * D);
#pragma unroll
        for (int q = 0; q < 4; q++) {
            float4 t0 = v0 ? p0[q] : make_float4(0.f, 0.f, 0.f, 0.f);
            float4 t1 = v1 ? p1[q] : make_float4(0.f, 0.f, 0.f, 0.f);
            za[4*q+0] = t0.x; za[4*q+1] = t0.y; za[4*q+2] = t0.z; za[4*q+3] = t0.w;
            zb[4*q+0] = t1.x; zb[4*q+1] = t1.y; zb[4*q+2] = t1.z; zb[4*q+3] = t1.w;
        }
    }
    // Stash z into smem [k][tid] so triangular loops can index dynamically
#pragma unroll
    for (int k = 0; k < D; k++) {
        zsA[k * TPB + tid] = za[k];
        zsB[k * TPB + tid] = zb[k];
    }
    __syncthreads();

    // 8 packed accumulators per row (16 fp32 outputs each)
    unsigned long long aA[8], aB[8];
    const unsigned long long* cp = (const unsigned long long*)scf;
#pragma unroll
    for (int p = 0; p < 8; p++) { aA[p] = cp[p]; aB[p] = cp[p]; }  // constant term (theta col 0 == 1)
    cp += 8;

    // One coefficient row: 4x LDS.128 (broadcast) + 16 FFMA2
#define ROW(mAf, mBf) do {                                              \
        unsigned long long mA_, mB_;                                    \
        PACK2(mA_, (mAf)); PACK2(mB_, (mBf));                           \
        ulonglong2 q0 = ((const ulonglong2*)cp)[0];                     \
        ulonglong2 q1 = ((const ulonglong2*)cp)[1];                     \
        ulonglong2 q2 = ((const ulonglong2*)cp)[2];                     \
        ulonglong2 q3 = ((const ulonglong2*)cp)[3];                     \
        FFMA2(aA[0], mA_, q0.x); FFMA2(aB[0], mB_, q0.x);               \
        FFMA2(aA[1], mA_, q0.y); FFMA2(aB[1], mB_, q0.y);               \
        FFMA2(aA[2], mA_, q1.x); FFMA2(aB[2], mB_, q1.x);               \
        FFMA2(aA[3], mA_, q1.y); FFMA2(aB[3], mB_, q1.y);               \
        FFMA2(aA[4], mA_, q2.x); FFMA2(aB[4], mB_, q2.x);               \
        FFMA2(aA[5], mA_, q2.y); FFMA2(aB[5], mB_, q2.y);               \
        FFMA2(aA[6], mA_, q3.x); FFMA2(aB[6], mB_, q3.x);               \
        FFMA2(aA[7], mA_, q3.y); FFMA2(aB[7], mB_, q3.y);               \
        cp += 8;                                                        \
    } while (0)

    // ---- order 1: z_i ----
    for (int i = 0; i < D; i++) {
        float ziA = zsA[i * TPB + tid];
        float ziB = zsB[i * TPB + tid];
        ROW(ziA, ziB);
    }
    // ---- order 2: z_i * z_j, i<=j (lexicographic == combinations_with_replacement) ----
    for (int i = 0; i < D; i++) {
        float ziA = zsA[i * TPB + tid];
        float ziB = zsB[i * TPB + tid];
        for (int j = i; j < D; j++) {
            float mA = ziA * zsA[j * TPB + tid];
            float mB = ziB * zsB[j * TPB + tid];
            ROW(mA, mB);
        }
    }
    // ---- order 3: z_i * z_j * z_k, i<=j<=k ----
    for (int i = 0; i < D; i++) {
        float ziA = zsA[i * TPB + tid];
        float ziB = zsB[i * TPB + tid];
        for (int j = i; j < D; j++) {
            float pA = ziA * zsA[j * TPB + tid];
            float pB = ziB * zsB[j * TPB + tid];
            for (int k = j; k < D; k++) {
                float mA = pA * zsA[k * TPB + tid];
                float mB = pB * zsB[k * TPB + tid];
                ROW(mA, mB);
            }
        }
    }
#undef ROW

    // Store 16 fp32 outputs per row as 4x 16B stores
    if (v0) {
        ulonglong2* o = (ulonglong2*)(out + r0 * D);
        o[0] = make_ulonglong2(aA[0], aA[1]);
        o[1] = make_ulonglong2(aA[2], aA[3]);
        o[2] = make_ulonglong2(aA[4], aA[5]);
        o[3] = make_ulonglong2(aA[6], aA[7]);
    }
    if (v1) {
        ulonglong2* o = (ulonglong2*)(out + r1 * D);
        o[0] = make_ulonglong2(aB[0], aB[1]);
        o[1] = make_ulonglong2(aB[2], aB[3]);
        o[2] = make_ulonglong2(aB[4], aB[5]);
        o[3] = make_ulonglong2(aB[6], aB[7]);
    }
}

extern "C" void kernel_launch(void* const* d_in, const int* in_sizes, int n_in,
                              void* d_out, int out_size)
{
    const float*         z      = (const float*)d_in[0];
    const float*         coeff  = (const float*)d_in[1];
    const float*         fixedv = (const float*)d_in[2];
    const unsigned char* fmask  = (const unsigned char*)d_in[3];
    float*               out    = (float*)d_out;

    const int B = in_sizes[0] / D;

    const int smem_bytes = (LIB * D + 2 * TPB * D) * (int)sizeof(float);
    cudaFuncSetAttribute(sindy_kernel,
                         cudaFuncAttributeMaxDynamicSharedMemorySize, smem_bytes);

    const int grid = (B + ROWS_PER_BLOCK - 1) / ROWS_PER_BLOCK;
    sindy_kernel<<<grid, TPB, smem_bytes>>>(z, coeff, fixedv, fmask, out, B);
}